// round 6
// baseline (speedup 1.0000x reference)
#include <cuda_runtime.h>
#include <cuda_bf16.h>
#include <cstdint>
#include <math.h>

// ---------------------------------------------------------------------------
// Shapes (fixed): T=2048, B=16, D=1024.  M = T*B = 32768, K = N = 1024.
//   xw = x @ W_x^T + b  via mma.sync bf16 hi/lo split (3 MMAs), fp32 accum.
//   scan: h_t = tanh(xw_t + d_c * h_{t-1}); out_t = h_t^2 * sigmoid(h_t)
//   d_out = [ output (T*B*D) | h ((T+1)*B*D) ]
// R6: GEMM and scan OVERLAP. GEMM publishes per-m-block completion counters;
// the scan (on a forked stream) gates on them and trails right behind.
// ---------------------------------------------------------------------------

#define KDIM 1024
#define BM 128
#define BN 128
#define BK 64                 // 64 bf16 = 128 B rows -> swizzled
#define NK (KDIM / BK)        // 16
#define NTILES (KDIM / BN)    // 8 n-tiles per m-block

__device__ __align__(128) float         g_xw [2048 * 16 * 1024];  // 128 MB
__device__ __align__(128) __nv_bfloat16 g_Ahi[32768 * 1024];      // 64 MB
__device__ __align__(128) __nv_bfloat16 g_Alo[32768 * 1024];      // 64 MB
__device__ __align__(128) __nv_bfloat16 g_Whi[1024 * 1024];       // 2 MB
__device__ __align__(128) __nv_bfloat16 g_Wlo[1024 * 1024];       // 2 MB
__device__ unsigned g_cnt[256];                                   // m-block counters

// ---------------------------------------------------------------------------
__device__ __forceinline__ void split4(float4 v, uint2& hi, uint2& lo) {
    __nv_bfloat16 hx = __float2bfloat16(v.x), hy = __float2bfloat16(v.y);
    __nv_bfloat16 hz = __float2bfloat16(v.z), hw = __float2bfloat16(v.w);
    __nv_bfloat16 lx = __float2bfloat16(v.x - __bfloat162float(hx));
    __nv_bfloat16 ly = __float2bfloat16(v.y - __bfloat162float(hy));
    __nv_bfloat16 lz = __float2bfloat16(v.z - __bfloat162float(hz));
    __nv_bfloat16 lw = __float2bfloat16(v.w - __bfloat162float(hw));
    __nv_bfloat162 h01 = __halves2bfloat162(hx, hy), h23 = __halves2bfloat162(hz, hw);
    __nv_bfloat162 l01 = __halves2bfloat162(lx, ly), l23 = __halves2bfloat162(lz, lw);
    hi.x = *reinterpret_cast<uint32_t*>(&h01); hi.y = *reinterpret_cast<uint32_t*>(&h23);
    lo.x = *reinterpret_cast<uint32_t*>(&l01); lo.y = *reinterpret_cast<uint32_t*>(&l23);
}
__global__ void splitA_kernel(const float4* __restrict__ src, int n4) {
    int i = blockIdx.x * blockDim.x + threadIdx.x;
    if (i >= n4) return;
    uint2 hi, lo; split4(src[i], hi, lo);
    reinterpret_cast<uint2*>(g_Ahi)[i] = hi;
    reinterpret_cast<uint2*>(g_Alo)[i] = lo;
}
__global__ void splitW_kernel(const float4* __restrict__ src, int n4) {
    int i = blockIdx.x * blockDim.x + threadIdx.x;
    if (i >= n4) return;
    uint2 hi, lo; split4(src[i], hi, lo);
    reinterpret_cast<uint2*>(g_Whi)[i] = hi;
    reinterpret_cast<uint2*>(g_Wlo)[i] = lo;
}
__global__ void reset_kernel() {
    if (threadIdx.x < 256) g_cnt[threadIdx.x] = 0u;
}

// ---------------------------------------------------------------------------
__device__ __forceinline__ uint32_t smem_u32(const void* p) {
    uint32_t a;
    asm("{ .reg .u64 t; cvta.to.shared.u64 t, %1; cvt.u32.u64 %0, t; }" : "=r"(a) : "l"(p));
    return a;
}
__device__ __forceinline__ void cp16(uint32_t dst, const void* src) {
    asm volatile("cp.async.cg.shared.global [%0], [%1], 16;" :: "r"(dst), "l"(src));
}
#define CP_COMMIT() asm volatile("cp.async.commit_group;" ::: "memory")
#define CP_WAIT(n)  asm volatile("cp.async.wait_group %0;" :: "n"(n) : "memory")

__device__ __forceinline__ void ldm_x4(uint32_t* r, uint32_t addr) {
    asm volatile("ldmatrix.sync.aligned.m8n8.x4.shared.b16 {%0,%1,%2,%3}, [%4];"
                 : "=r"(r[0]), "=r"(r[1]), "=r"(r[2]), "=r"(r[3]) : "r"(addr));
}
__device__ __forceinline__ void mma16816(float* d, const uint32_t* a,
                                         const uint32_t* b) {
    asm volatile(
        "mma.sync.aligned.m16n8k16.row.col.f32.bf16.bf16.f32 "
        "{%0,%1,%2,%3}, {%4,%5,%6,%7}, {%8,%9}, {%0,%1,%2,%3};"
        : "+f"(d[0]), "+f"(d[1]), "+f"(d[2]), "+f"(d[3])
        : "r"(a[0]), "r"(a[1]), "r"(a[2]), "r"(a[3]), "r"(b[0]), "r"(b[1]));
}
__device__ __forceinline__ unsigned ldacq(const unsigned* p) {
    unsigned v;
    asm volatile("ld.acquire.gpu.u32 %0, [%1];" : "=r"(v) : "l"(p) : "memory");
    return v;
}

// SMEM: per stage: Ahi(16K) Alo(16K) Whi(16K) Wlo(16K) = 64 KB; 2 stages.
#define STG_BYTES   (64 * 1024)
#define OFF_AH      0
#define OFF_AL      (16 * 1024)
#define OFF_BH      (32 * 1024)
#define OFF_BL      (48 * 1024)
#define SMEM_TOTAL  (2 * STG_BYTES)

__device__ __forceinline__ uint32_t tswz(int row, int c) {
    return (uint32_t)(row * 128 + ((c ^ (row & 7)) * 16));
}

// ---------------------------------------------------------------------------
// GEMM (R3 config: BN=128, pre-split A, 8 warps) + completion counters.
// ---------------------------------------------------------------------------
__global__ __launch_bounds__(256, 1)
void gemm_mma_kernel(const float* __restrict__ bias) {
    extern __shared__ char smem[];
    const uint32_t sb = smem_u32(smem);
    const int tid = threadIdx.x;
    const int wid = tid >> 5;
    const int lane = tid & 31;
    const int m0 = blockIdx.y * BM;
    const int n0 = blockIdx.x * BN;

    const int warp_m = wid & 3;    // 0..3 -> 32 rows
    const int warp_n = wid >> 2;   // 0..1 -> 64 cols

    const int lrow = tid >> 1;
    const int lc0  = (tid & 1) * 4;

    auto stage_in = [&](int kt, int stg) {
        const uint32_t base = sb + stg * STG_BYTES;
        const size_t ga = (size_t)(m0 + lrow) * KDIM + kt * BK;
        const size_t gb = (size_t)(n0 + lrow) * KDIM + kt * BK;
#pragma unroll
        for (int j = 0; j < 4; ++j) {
            const int c = lc0 + j;
            const uint32_t so = tswz(lrow, c);
            cp16(base + OFF_AH + so, g_Ahi + ga + c * 8);
            cp16(base + OFF_AL + so, g_Alo + ga + c * 8);
            cp16(base + OFF_BH + so, g_Whi + gb + c * 8);
            cp16(base + OFF_BL + so, g_Wlo + gb + c * 8);
        }
        CP_COMMIT();
    };

    float acc[2][8][4];
#pragma unroll
    for (int i = 0; i < 2; ++i)
#pragma unroll
        for (int j = 0; j < 8; ++j)
#pragma unroll
            for (int q = 0; q < 4; ++q) acc[i][j][q] = 0.0f;

    stage_in(0, 0);

    const int lmat  = lane >> 3;
    const int lrow8 = lane & 7;

    for (int kt = 0; kt < NK; ++kt) {
        if (kt + 1 < NK) stage_in(kt + 1, (kt + 1) & 1);
        if (kt + 1 < NK) { CP_WAIT(1); } else { CP_WAIT(0); }
        __syncthreads();

        const uint32_t base = sb + (kt & 1) * STG_BYTES;

#pragma unroll
        for (int kk = 0; kk < 4; ++kk) {
            uint32_t afh[2][4], afl[2][4];
#pragma unroll
            for (int mt = 0; mt < 2; ++mt) {
                const int r = warp_m * 32 + mt * 16 + (lmat & 1) * 8 + lrow8;
                const int c = 2 * kk + (lmat >> 1);
                const uint32_t so = tswz(r, c);
                ldm_x4(afh[mt], base + OFF_AH + so);
                ldm_x4(afl[mt], base + OFF_AL + so);
            }
            uint32_t bfh[4][4], bfl[4][4];
#pragma unroll
            for (int bt = 0; bt < 4; ++bt) {
                const int r = warp_n * 64 + bt * 16 + (lmat >> 1) * 8 + lrow8;
                const int c = 2 * kk + (lmat & 1);
                const uint32_t so = tswz(r, c);
                ldm_x4(bfh[bt], base + OFF_BH + so);
                ldm_x4(bfl[bt], base + OFF_BL + so);
            }
#pragma unroll
            for (int mt = 0; mt < 2; ++mt)
#pragma unroll
                for (int nt = 0; nt < 8; ++nt) {
                    const int bt = nt >> 1;
                    const int bo = (nt & 1) * 2;
                    mma16816(acc[mt][nt], afh[mt], &bfh[bt][bo]);   // hi*hi
                    mma16816(acc[mt][nt], afh[mt], &bfl[bt][bo]);   // hi*lo
                    mma16816(acc[mt][nt], afl[mt], &bfh[bt][bo]);   // lo*hi
                }
        }
        __syncthreads();
    }

    // Epilogue: add bias, store fp32 to g_xw
    const int g   = lane >> 2;
    const int tig = lane & 3;
#pragma unroll
    for (int mt = 0; mt < 2; ++mt) {
#pragma unroll
        for (int nt = 0; nt < 8; ++nt) {
            const int row = m0 + warp_m * 32 + mt * 16 + g;
            const int col = n0 + warp_n * 64 + nt * 8 + tig * 2;
            const float b0 = __ldg(bias + col);
            const float b1 = __ldg(bias + col + 1);
            float2 v0 = make_float2(acc[mt][nt][0] + b0, acc[mt][nt][1] + b1);
            float2 v1 = make_float2(acc[mt][nt][2] + b0, acc[mt][nt][3] + b1);
            *reinterpret_cast<float2*>(g_xw + (size_t)row * KDIM + col)       = v0;
            *reinterpret_cast<float2*>(g_xw + (size_t)(row + 8) * KDIM + col) = v1;
        }
    }

    // Publish: this (mtile, ntile) is done.
    __syncthreads();
    if (tid == 0) {
        __threadfence();
        atomicAdd(&g_cnt[blockIdx.y], 1u);
    }
}

// ---------------------------------------------------------------------------
// Gated recurrent scan: trails the GEMM. One m-block = 8 timesteps (BM/B).
// Gate BEFORE loading a block (no stale-L1 risk). HW tanh for recurrence
// and output sigmoid (validated ~1e-5 rel_err).
// ---------------------------------------------------------------------------
__global__ __launch_bounds__(128)
void scan_kernel(const float* __restrict__ h0,
                 const float* __restrict__ dvec,
                 float* __restrict__ out,
                 int T, int BD, int D)
{
    const int idx = blockIdx.x * blockDim.x + threadIdx.x;

    float dc = dvec[idx & (D - 1)];
    dc = fminf(fmaxf(dc, -0.99f), 0.99f);

    float h = h0[idx];
    float* __restrict__ out_h = out + (size_t)T * BD;
    __stcs(out_h + idx, h);

    const float* __restrict__ p = g_xw + idx;
    const size_t s = (size_t)BD;

    auto gate = [&](int mb) {
        if (threadIdx.x == 0) {
            while (ldacq(&g_cnt[mb]) < (unsigned)NTILES) __nanosleep(128);
        }
        __syncthreads();
    };

    gate(0);
    float cur[8];
#pragma unroll
    for (int u = 0; u < 8; ++u) cur[u] = __ldcs(p + u * s);

    for (int t0 = 0; t0 < T; t0 += 8) {
        const int mb = t0 >> 3;
        float nxt[8];
        const bool more = (t0 + 8 < T);
        if (more) {
            gate(mb + 1);
            const float* pn = p + (size_t)(t0 + 8) * s;
#pragma unroll
            for (int u = 0; u < 8; ++u) nxt[u] = __ldcs(pn + u * s);
        }
        float* __restrict__ po = out + (size_t)t0 * BD + idx;
        float* __restrict__ ph = out_h + (size_t)(t0 + 1) * BD + idx;
#pragma unroll
        for (int u = 0; u < 8; ++u) {
            const float z = fmaf(dc, h, cur[u]);
            asm("tanh.approx.f32 %0, %1;" : "=f"(h) : "f"(z));       // h = tanh(z)
            float th;
            asm("tanh.approx.f32 %0, %1;" : "=f"(th) : "f"(0.5f * h));
            const float sg = fmaf(0.5f, th, 0.5f);                    // sigmoid(h)
            __stcs(po + (size_t)u * BD, h * h * sg);                  // h * silu(h)
            __stcs(ph + (size_t)u * BD, h);
        }
#pragma unroll
        for (int u = 0; u < 8; ++u) cur[u] = nxt[u];
    }
}

// ---------------------------------------------------------------------------
// kernel_launch: splits + reset, then GEMM || scan (fork-join via events).
// Stream/events created once, during the (uncaptured) correctness call.
// ---------------------------------------------------------------------------
extern "C" void kernel_launch(void* const* d_in, const int* in_sizes, int n_in,
                              void* d_out, int out_size)
{
    (void)n_in; (void)out_size;
    const float* x  = (const float*)d_in[0];
    const float* h0 = (const float*)d_in[1];
    const float* W  = (const float*)d_in[2];
    const float* dv = (const float*)d_in[3];
    const float* b  = (const float*)d_in[4];
    float* out = (float*)d_out;

    const int D  = in_sizes[3];           // 1024
    const int BD = in_sizes[1];           // 16384
    const int T  = in_sizes[0] / BD;      // 2048
    const int M  = in_sizes[0] / D;       // 32768

    static cudaStream_t s2 = nullptr;
    static cudaEvent_t evFork = nullptr, evJoin = nullptr;
    if (s2 == nullptr) {
        cudaStreamCreateWithFlags(&s2, cudaStreamNonBlocking);
        cudaEventCreateWithFlags(&evFork, cudaEventDisableTiming);
        cudaEventCreateWithFlags(&evJoin, cudaEventDisableTiming);
        cudaFuncSetAttribute(gemm_mma_kernel,
                             cudaFuncAttributeMaxDynamicSharedMemorySize, SMEM_TOTAL);
    }

    const int nA4 = (M * D) / 4;
    splitA_kernel<<<nA4 / 256, 256>>>((const float4*)x, nA4);
    const int nW4 = (D * D) / 4;
    splitW_kernel<<<(nW4 + 255) / 256, 256>>>((const float4*)W, nW4);
    reset_kernel<<<1, 256>>>();

    // Fork: scan runs concurrently with the GEMM, gated by g_cnt.
    cudaEventRecord(evFork, 0);
    cudaStreamWaitEvent(s2, evFork, 0);

    dim3 grid(D / BN, M / BM);            // (8, 256), y-major production order
    gemm_mma_kernel<<<grid, 256, SMEM_TOTAL>>>(b);

    scan_kernel<<<BD / 128, 128, 0, s2>>>(h0, dv, out, T, BD, D);

    // Join back to the default stream.
    cudaEventRecord(evJoin, s2);
    cudaStreamWaitEvent(0, evJoin, 0);
}

// round 7
// speedup vs baseline: 1.1143x; 1.1143x over previous
#include <cuda_runtime.h>
#include <cuda_bf16.h>
#include <cstdint>
#include <math.h>

// ---------------------------------------------------------------------------
// Shapes (fixed): T=2048, B=16, D=1024.  M = T*B = 32768, K = N = 1024.
//   xw = x @ W_x^T + b  via mma.sync bf16 hi/lo split (3 MMAs), fp32 accum.
//   A (=x) split fp32->bf16 hi/lo inside the GEMM; W pre-split once (4 MB).
//   scan: h_t = tanh(xw_t + d_c * h_{t-1}); out_t = h_t^2 * sigmoid(h_t)
//   d_out = [ output (T*B*D) | h ((T+1)*B*D) ]
// R7: MMA pass reorder — 3 split passes issued as 16 independent MMAs each,
// breaking the per-accumulator RAW chains that held tensor pipe at 52%.
// ---------------------------------------------------------------------------

#define KDIM 1024
#define BM 128
#define BN 128
#define BK 64                 // 64 bf16 = 128 B rows -> swizzled
#define NK (KDIM / BK)        // 16

__device__ __align__(128) float         g_xw [2048 * 16 * 1024];  // 128 MB
__device__ __align__(128) __nv_bfloat16 g_Whi[1024 * 1024];       // 2 MB
__device__ __align__(128) __nv_bfloat16 g_Wlo[1024 * 1024];       // 2 MB

// ---------------------------------------------------------------------------
__device__ __forceinline__ void split4(float4 v, uint2& hi, uint2& lo) {
    __nv_bfloat16 hx = __float2bfloat16(v.x), hy = __float2bfloat16(v.y);
    __nv_bfloat16 hz = __float2bfloat16(v.z), hw = __float2bfloat16(v.w);
    __nv_bfloat16 lx = __float2bfloat16(v.x - __bfloat162float(hx));
    __nv_bfloat16 ly = __float2bfloat16(v.y - __bfloat162float(hy));
    __nv_bfloat16 lz = __float2bfloat16(v.z - __bfloat162float(hz));
    __nv_bfloat16 lw = __float2bfloat16(v.w - __bfloat162float(hw));
    __nv_bfloat162 h01 = __halves2bfloat162(hx, hy), h23 = __halves2bfloat162(hz, hw);
    __nv_bfloat162 l01 = __halves2bfloat162(lx, ly), l23 = __halves2bfloat162(lz, lw);
    hi.x = *reinterpret_cast<uint32_t*>(&h01); hi.y = *reinterpret_cast<uint32_t*>(&h23);
    lo.x = *reinterpret_cast<uint32_t*>(&l01); lo.y = *reinterpret_cast<uint32_t*>(&l23);
}
__global__ void splitW_kernel(const float4* __restrict__ src, int n4) {
    int i = blockIdx.x * blockDim.x + threadIdx.x;
    if (i >= n4) return;
    uint2 hi, lo; split4(src[i], hi, lo);
    reinterpret_cast<uint2*>(g_Whi)[i] = hi;
    reinterpret_cast<uint2*>(g_Wlo)[i] = lo;
}

// ---------------------------------------------------------------------------
__device__ __forceinline__ uint32_t smem_u32(const void* p) {
    uint32_t a;
    asm("{ .reg .u64 t; cvta.to.shared.u64 t, %1; cvt.u32.u64 %0, t; }" : "=r"(a) : "l"(p));
    return a;
}
__device__ __forceinline__ void cp16(uint32_t dst, const void* src) {
    asm volatile("cp.async.cg.shared.global [%0], [%1], 16;" :: "r"(dst), "l"(src));
}
#define CP_COMMIT() asm volatile("cp.async.commit_group;" ::: "memory")
#define CP_WAIT(n)  asm volatile("cp.async.wait_group %0;" :: "n"(n) : "memory")

__device__ __forceinline__ void ldm_x4(uint32_t* r, uint32_t addr) {
    asm volatile("ldmatrix.sync.aligned.m8n8.x4.shared.b16 {%0,%1,%2,%3}, [%4];"
                 : "=r"(r[0]), "=r"(r[1]), "=r"(r[2]), "=r"(r[3]) : "r"(addr));
}
__device__ __forceinline__ void mma16816(float* d, const uint32_t* a,
                                         const uint32_t* b) {
    asm volatile(
        "mma.sync.aligned.m16n8k16.row.col.f32.bf16.bf16.f32 "
        "{%0,%1,%2,%3}, {%4,%5,%6,%7}, {%8,%9}, {%0,%1,%2,%3};"
        : "+f"(d[0]), "+f"(d[1]), "+f"(d[2]), "+f"(d[3])
        : "r"(a[0]), "r"(a[1]), "r"(a[2]), "r"(a[3]), "r"(b[0]), "r"(b[1]));
}

// SMEM: per stage: Ahi(16K) Alo(16K) Whi(16K) Wlo(16K) = 64 KB; 2 stages.
#define STG_BYTES   (64 * 1024)
#define OFF_AH      0
#define OFF_AL      (16 * 1024)
#define OFF_BH      (32 * 1024)
#define OFF_BL      (48 * 1024)
#define SMEM_TOTAL  (2 * STG_BYTES)

__device__ __forceinline__ uint32_t tswz(int row, int c) {
    return (uint32_t)(row * 128 + ((c ^ (row & 7)) * 16));
}

// ---------------------------------------------------------------------------
// GEMM: g_xw[m,n] = sum_k x[m,k]*W[n,k] + bias[n]
// 256 threads, 8 warps: warp_m = wid&3 (32 rows), warp_n = wid>>2 (64 cols).
// A: LDG fp32 -> reg convert -> STS bf16 hi/lo.  W: cp.async pre-split.
// MMA inner loop: 3 passes x 16 independent accumulators (pipelined).
// ---------------------------------------------------------------------------
__global__ __launch_bounds__(256, 1)
void gemm_mma_kernel(const float* __restrict__ x, const float* __restrict__ bias) {
    extern __shared__ char smem[];
    const uint32_t sb = smem_u32(smem);
    const int tid = threadIdx.x;
    const int wid = tid >> 5;
    const int lane = tid & 31;
    const int m0 = blockIdx.y * BM;
    const int n0 = blockIdx.x * BN;

    const int warp_m = wid & 3;    // 0..3 -> 32 rows
    const int warp_n = wid >> 2;   // 0..1 -> 64 cols

    const int lrow = tid >> 1;
    const int lc0  = (tid & 1) * 4;

    auto stageW = [&](int kt, int stg) {
        const uint32_t base = sb + stg * STG_BYTES;
        const size_t gb = (size_t)(n0 + lrow) * KDIM + kt * BK;
#pragma unroll
        for (int j = 0; j < 4; ++j) {
            const int c = lc0 + j;
            const uint32_t so = tswz(lrow, c);
            cp16(base + OFF_BH + so, g_Whi + gb + c * 8);
            cp16(base + OFF_BL + so, g_Wlo + gb + c * 8);
        }
        CP_COMMIT();
    };
    auto ldgA = [&](int kt, float4* a8) {
        const float4* src = reinterpret_cast<const float4*>(
            x + (size_t)(m0 + lrow) * KDIM + kt * BK + lc0 * 8);
#pragma unroll
        for (int j = 0; j < 8; ++j) a8[j] = __ldg(src + j);
    };
    auto cvtA = [&](const float4* a8, int stg) {
        char* base = smem + stg * STG_BYTES;
#pragma unroll
        for (int j = 0; j < 4; ++j) {
            uint2 h0, l0, h1, l1;
            split4(a8[2 * j], h0, l0);
            split4(a8[2 * j + 1], h1, l1);
            const uint32_t so = tswz(lrow, lc0 + j);
            *reinterpret_cast<uint4*>(base + OFF_AH + so) = make_uint4(h0.x, h0.y, h1.x, h1.y);
            *reinterpret_cast<uint4*>(base + OFF_AL + so) = make_uint4(l0.x, l0.y, l1.x, l1.y);
        }
    };

    float acc[2][8][4];
#pragma unroll
    for (int i = 0; i < 2; ++i)
#pragma unroll
        for (int j = 0; j < 8; ++j)
#pragma unroll
            for (int q = 0; q < 4; ++q) acc[i][j][q] = 0.0f;

    // Prologue
    {
        float4 a8[8];
        ldgA(0, a8);
        stageW(0, 0);
        cvtA(a8, 0);
        CP_WAIT(0);
        __syncthreads();
    }

    const int lmat  = lane >> 3;
    const int lrow8 = lane & 7;

    for (int kt = 0; kt < NK; ++kt) {
        const int stg = kt & 1;
        const bool more = (kt + 1 < NK);
        float4 a8[8];
        if (more) { ldgA(kt + 1, a8); stageW(kt + 1, stg ^ 1); }

        const uint32_t base = sb + stg * STG_BYTES;
#pragma unroll
        for (int kk = 0; kk < 4; ++kk) {
            uint32_t afh[2][4], afl[2][4];
#pragma unroll
            for (int mt = 0; mt < 2; ++mt) {
                const int r = warp_m * 32 + mt * 16 + (lmat & 1) * 8 + lrow8;
                const int c = 2 * kk + (lmat >> 1);
                const uint32_t so = tswz(r, c);
                ldm_x4(afh[mt], base + OFF_AH + so);
                ldm_x4(afl[mt], base + OFF_AL + so);
            }
            uint32_t bfh[4][4], bfl[4][4];
#pragma unroll
            for (int bt = 0; bt < 4; ++bt) {
                const int r = warp_n * 64 + bt * 16 + (lmat >> 1) * 8 + lrow8;
                const int c = 2 * kk + (lmat & 1);
                const uint32_t so = tswz(r, c);
                ldm_x4(bfh[bt], base + OFF_BH + so);
                ldm_x4(bfl[bt], base + OFF_BL + so);
            }
            // Pass 1: hi*hi — 16 independent accumulators, fully pipelined.
#pragma unroll
            for (int mt = 0; mt < 2; ++mt)
#pragma unroll
                for (int nt = 0; nt < 8; ++nt)
                    mma16816(acc[mt][nt], afh[mt], &bfh[nt >> 1][(nt & 1) * 2]);
            // Pass 2: hi*lo
#pragma unroll
            for (int mt = 0; mt < 2; ++mt)
#pragma unroll
                for (int nt = 0; nt < 8; ++nt)
                    mma16816(acc[mt][nt], afh[mt], &bfl[nt >> 1][(nt & 1) * 2]);
            // Pass 3: lo*hi
#pragma unroll
            for (int mt = 0; mt < 2; ++mt)
#pragma unroll
                for (int nt = 0; nt < 8; ++nt)
                    mma16816(acc[mt][nt], afl[mt], &bfh[nt >> 1][(nt & 1) * 2]);
        }

        if (more) {
            cvtA(a8, stg ^ 1);
            CP_WAIT(0);
        }
        __syncthreads();
    }

    // Epilogue: add bias, store fp32 to g_xw
    const int g   = lane >> 2;
    const int tig = lane & 3;
#pragma unroll
    for (int mt = 0; mt < 2; ++mt) {
#pragma unroll
        for (int nt = 0; nt < 8; ++nt) {
            const int row = m0 + warp_m * 32 + mt * 16 + g;
            const int col = n0 + warp_n * 64 + nt * 8 + tig * 2;
            const float b0 = __ldg(bias + col);
            const float b1 = __ldg(bias + col + 1);
            float2 v0 = make_float2(acc[mt][nt][0] + b0, acc[mt][nt][1] + b1);
            float2 v1 = make_float2(acc[mt][nt][2] + b0, acc[mt][nt][3] + b1);
            *reinterpret_cast<float2*>(g_xw + (size_t)row * KDIM + col)       = v0;
            *reinterpret_cast<float2*>(g_xw + (size_t)(row + 8) * KDIM + col) = v1;
        }
    }
}

// ---------------------------------------------------------------------------
// Recurrent scan (validated): HW tanh.approx for recurrence + output sigmoid,
// PF=32 prefetch, streaming cache hints.
// ---------------------------------------------------------------------------
#define PF 32
__global__ __launch_bounds__(128)
void scan_kernel(const float* __restrict__ h0,
                 const float* __restrict__ dvec,
                 float* __restrict__ out,
                 int T, int BD, int D)
{
    const int idx = blockIdx.x * blockDim.x + threadIdx.x;
    if (idx >= BD) return;

    float dc = dvec[idx & (D - 1)];
    dc = fminf(fmaxf(dc, -0.99f), 0.99f);

    float h = h0[idx];
    float* __restrict__ out_h = out + (size_t)T * BD;
    __stcs(out_h + idx, h);

    const float* __restrict__ p = g_xw + idx;
    const size_t s = (size_t)BD;

    float cur[PF];
#pragma unroll
    for (int u = 0; u < PF; ++u) cur[u] = __ldcs(p + u * s);

    for (int t0 = 0; t0 < T; t0 += PF) {
        float nxt[PF];
        if (t0 + PF < T) {
            const float* pn = p + (size_t)(t0 + PF) * s;
#pragma unroll
            for (int u = 0; u < PF; ++u) nxt[u] = __ldcs(pn + u * s);
        } else {
#pragma unroll
            for (int u = 0; u < PF; ++u) nxt[u] = 0.0f;
        }
        float* __restrict__ po = out + (size_t)t0 * BD + idx;
        float* __restrict__ ph = out_h + (size_t)(t0 + 1) * BD + idx;
#pragma unroll
        for (int u = 0; u < PF; ++u) {
            const float z = fmaf(dc, h, cur[u]);
            asm("tanh.approx.f32 %0, %1;" : "=f"(h) : "f"(z));       // h = tanh(z)
            float th;
            asm("tanh.approx.f32 %0, %1;" : "=f"(th) : "f"(0.5f * h));
            const float sg = fmaf(0.5f, th, 0.5f);                    // sigmoid(h)
            __stcs(po + (size_t)u * BD, h * h * sg);                  // h * silu(h)
            __stcs(ph + (size_t)u * BD, h);
        }
#pragma unroll
        for (int u = 0; u < PF; ++u) cur[u] = nxt[u];
    }
}

// ---------------------------------------------------------------------------
// kernel_launch: splitW -> GEMM -> scan (serial; overlap regressed in R6).
// ---------------------------------------------------------------------------
extern "C" void kernel_launch(void* const* d_in, const int* in_sizes, int n_in,
                              void* d_out, int out_size)
{
    (void)n_in; (void)out_size;
    const float* x  = (const float*)d_in[0];
    const float* h0 = (const float*)d_in[1];
    const float* W  = (const float*)d_in[2];
    const float* dv = (const float*)d_in[3];
    const float* b  = (const float*)d_in[4];
    float* out = (float*)d_out;

    const int D  = in_sizes[3];           // 1024
    const int BD = in_sizes[1];           // 16384
    const int T  = in_sizes[0] / BD;      // 2048
    const int M  = in_sizes[0] / D;       // 32768

    const int nW4 = (D * D) / 4;
    splitW_kernel<<<(nW4 + 255) / 256, 256>>>((const float4*)W, nW4);

    cudaFuncSetAttribute(gemm_mma_kernel,
                         cudaFuncAttributeMaxDynamicSharedMemorySize, SMEM_TOTAL);
    dim3 grid(D / BN, M / BM);            // (8, 256)
    gemm_mma_kernel<<<grid, 256, SMEM_TOTAL>>>(x, b);

    scan_kernel<<<(BD + 127) / 128, 128>>>(h0, dv, out, T, BD, D);
}

// round 8
// speedup vs baseline: 1.2407x; 1.1134x over previous
#include <cuda_runtime.h>
#include <cuda_bf16.h>
#include <cstdint>
#include <math.h>

// ---------------------------------------------------------------------------
// Shapes (fixed): T=2048, B=16, D=1024.  M = T*B = 32768, K = N = 1024.
//   xw = x @ W_x^T + b  via mma.sync bf16 hi/lo split (3 MMAs), fp32 accum.
//   A (=x) split fp32->bf16 hi/lo inside the GEMM; W pre-split once (4 MB).
//   scan: h_t = tanh(xw_t + d_c * h_{t-1}); out_t = h_t^2 * sigmoid(h_t)
//   d_out = [ output (T*B*D) | h ((T+1)*B*D) ]
// R8: 512-thread GEMM CTA (16 warps -> 4 warps/SMSP), 32x32 warp tiles.
// ---------------------------------------------------------------------------

#define KDIM 1024
#define BM 128
#define BN 128
#define BK 64                 // 64 bf16 = 128 B rows -> swizzled
#define NK (KDIM / BK)        // 16

__device__ __align__(128) float         g_xw [2048 * 16 * 1024];  // 128 MB
__device__ __align__(128) __nv_bfloat16 g_Whi[1024 * 1024];       // 2 MB
__device__ __align__(128) __nv_bfloat16 g_Wlo[1024 * 1024];       // 2 MB

// ---------------------------------------------------------------------------
__device__ __forceinline__ void split4(float4 v, uint2& hi, uint2& lo) {
    __nv_bfloat16 hx = __float2bfloat16(v.x), hy = __float2bfloat16(v.y);
    __nv_bfloat16 hz = __float2bfloat16(v.z), hw = __float2bfloat16(v.w);
    __nv_bfloat16 lx = __float2bfloat16(v.x - __bfloat162float(hx));
    __nv_bfloat16 ly = __float2bfloat16(v.y - __bfloat162float(hy));
    __nv_bfloat16 lz = __float2bfloat16(v.z - __bfloat162float(hz));
    __nv_bfloat16 lw = __float2bfloat16(v.w - __bfloat162float(hw));
    __nv_bfloat162 h01 = __halves2bfloat162(hx, hy), h23 = __halves2bfloat162(hz, hw);
    __nv_bfloat162 l01 = __halves2bfloat162(lx, ly), l23 = __halves2bfloat162(lz, lw);
    hi.x = *reinterpret_cast<uint32_t*>(&h01); hi.y = *reinterpret_cast<uint32_t*>(&h23);
    lo.x = *reinterpret_cast<uint32_t*>(&l01); lo.y = *reinterpret_cast<uint32_t*>(&l23);
}
__global__ void splitW_kernel(const float4* __restrict__ src, int n4) {
    int i = blockIdx.x * blockDim.x + threadIdx.x;
    if (i >= n4) return;
    uint2 hi, lo; split4(src[i], hi, lo);
    reinterpret_cast<uint2*>(g_Whi)[i] = hi;
    reinterpret_cast<uint2*>(g_Wlo)[i] = lo;
}

// ---------------------------------------------------------------------------
__device__ __forceinline__ uint32_t smem_u32(const void* p) {
    uint32_t a;
    asm("{ .reg .u64 t; cvta.to.shared.u64 t, %1; cvt.u32.u64 %0, t; }" : "=r"(a) : "l"(p));
    return a;
}
__device__ __forceinline__ void cp16(uint32_t dst, const void* src) {
    asm volatile("cp.async.cg.shared.global [%0], [%1], 16;" :: "r"(dst), "l"(src));
}
#define CP_COMMIT() asm volatile("cp.async.commit_group;" ::: "memory")
#define CP_WAIT(n)  asm volatile("cp.async.wait_group %0;" :: "n"(n) : "memory")

__device__ __forceinline__ void ldm_x4(uint32_t* r, uint32_t addr) {
    asm volatile("ldmatrix.sync.aligned.m8n8.x4.shared.b16 {%0,%1,%2,%3}, [%4];"
                 : "=r"(r[0]), "=r"(r[1]), "=r"(r[2]), "=r"(r[3]) : "r"(addr));
}
__device__ __forceinline__ void mma16816(float* d, const uint32_t* a,
                                         const uint32_t* b) {
    asm volatile(
        "mma.sync.aligned.m16n8k16.row.col.f32.bf16.bf16.f32 "
        "{%0,%1,%2,%3}, {%4,%5,%6,%7}, {%8,%9}, {%0,%1,%2,%3};"
        : "+f"(d[0]), "+f"(d[1]), "+f"(d[2]), "+f"(d[3])
        : "r"(a[0]), "r"(a[1]), "r"(a[2]), "r"(a[3]), "r"(b[0]), "r"(b[1]));
}

// SMEM: per stage: Ahi(16K) Alo(16K) Whi(16K) Wlo(16K) = 64 KB; 2 stages.
#define STG_BYTES   (64 * 1024)
#define OFF_AH      0
#define OFF_AL      (16 * 1024)
#define OFF_BH      (32 * 1024)
#define OFF_BL      (48 * 1024)
#define SMEM_TOTAL  (2 * STG_BYTES)

__device__ __forceinline__ uint32_t tswz(int row, int c) {
    return (uint32_t)(row * 128 + ((c ^ (row & 7)) * 16));
}

// ---------------------------------------------------------------------------
// GEMM: g_xw[m,n] = sum_k x[m,k]*W[n,k] + bias[n]
// 512 threads, 16 warps: warp_m = wid&3 (32 rows), warp_n = wid>>2 (32 cols).
// A: LDG fp32 -> reg convert -> STS bf16 hi/lo.  W: cp.async pre-split.
// MMA inner loop: 3 passes x 8 independent accumulators each (pipelined).
// ---------------------------------------------------------------------------
__global__ __launch_bounds__(512, 1)
void gemm_mma_kernel(const float* __restrict__ x, const float* __restrict__ bias) {
    extern __shared__ char smem[];
    const uint32_t sb = smem_u32(smem);
    const int tid = threadIdx.x;
    const int wid = tid >> 5;
    const int lane = tid & 31;
    const int m0 = blockIdx.y * BM;
    const int n0 = blockIdx.x * BN;

    const int warp_m = wid & 3;    // 0..3 -> 32 rows
    const int warp_n = wid >> 2;   // 0..3 -> 32 cols

    // Loaders: 4 threads/row, each thread 2 x 16B chunks.
    const int lrow = tid >> 2;           // 0..127
    const int lc0  = (tid & 3) * 2;      // chunk pair base (0,2,4,6)

    auto stageW = [&](int kt, int stg) {
        const uint32_t base = sb + stg * STG_BYTES;
        const size_t gb = (size_t)(n0 + lrow) * KDIM + kt * BK;
#pragma unroll
        for (int j = 0; j < 2; ++j) {
            const int c = lc0 + j;
            const uint32_t so = tswz(lrow, c);
            cp16(base + OFF_BH + so, g_Whi + gb + c * 8);
            cp16(base + OFF_BL + so, g_Wlo + gb + c * 8);
        }
        CP_COMMIT();
    };
    // A: 4 float4 = 16 fp32 = two 8-element chunks
    auto ldgA = [&](int kt, float4* a4) {
        const float4* src = reinterpret_cast<const float4*>(
            x + (size_t)(m0 + lrow) * KDIM + kt * BK + lc0 * 8);
#pragma unroll
        for (int j = 0; j < 4; ++j) a4[j] = __ldg(src + j);
    };
    auto cvtA = [&](const float4* a4, int stg) {
        char* base = smem + stg * STG_BYTES;
#pragma unroll
        for (int j = 0; j < 2; ++j) {
            uint2 h0, l0, h1, l1;
            split4(a4[2 * j], h0, l0);
            split4(a4[2 * j + 1], h1, l1);
            const uint32_t so = tswz(lrow, lc0 + j);
            *reinterpret_cast<uint4*>(base + OFF_AH + so) = make_uint4(h0.x, h0.y, h1.x, h1.y);
            *reinterpret_cast<uint4*>(base + OFF_AL + so) = make_uint4(l0.x, l0.y, l1.x, l1.y);
        }
    };

    float acc[2][4][4];
#pragma unroll
    for (int i = 0; i < 2; ++i)
#pragma unroll
        for (int j = 0; j < 4; ++j)
#pragma unroll
            for (int q = 0; q < 4; ++q) acc[i][j][q] = 0.0f;

    // Prologue
    {
        float4 a4[4];
        ldgA(0, a4);
        stageW(0, 0);
        cvtA(a4, 0);
        CP_WAIT(0);
        __syncthreads();
    }

    const int lmat  = lane >> 3;
    const int lrow8 = lane & 7;

    for (int kt = 0; kt < NK; ++kt) {
        const int stg = kt & 1;
        const bool more = (kt + 1 < NK);
        float4 a4[4];
        if (more) { ldgA(kt + 1, a4); stageW(kt + 1, stg ^ 1); }

        const uint32_t base = sb + stg * STG_BYTES;
#pragma unroll
        for (int kk = 0; kk < 4; ++kk) {
            uint32_t afh[2][4], afl[2][4];
#pragma unroll
            for (int mt = 0; mt < 2; ++mt) {
                const int r = warp_m * 32 + mt * 16 + (lmat & 1) * 8 + lrow8;
                const int c = 2 * kk + (lmat >> 1);
                const uint32_t so = tswz(r, c);
                ldm_x4(afh[mt], base + OFF_AH + so);
                ldm_x4(afl[mt], base + OFF_AL + so);
            }
            uint32_t bfh[2][4], bfl[2][4];
#pragma unroll
            for (int bt = 0; bt < 2; ++bt) {
                const int r = warp_n * 32 + bt * 16 + (lmat >> 1) * 8 + lrow8;
                const int c = 2 * kk + (lmat & 1);
                const uint32_t so = tswz(r, c);
                ldm_x4(bfh[bt], base + OFF_BH + so);
                ldm_x4(bfl[bt], base + OFF_BL + so);
            }
            // Pass 1: hi*hi — 8 independent accumulators.
#pragma unroll
            for (int mt = 0; mt < 2; ++mt)
#pragma unroll
                for (int nt = 0; nt < 4; ++nt)
                    mma16816(acc[mt][nt], afh[mt], &bfh[nt >> 1][(nt & 1) * 2]);
            // Pass 2: hi*lo
#pragma unroll
            for (int mt = 0; mt < 2; ++mt)
#pragma unroll
                for (int nt = 0; nt < 4; ++nt)
                    mma16816(acc[mt][nt], afh[mt], &bfl[nt >> 1][(nt & 1) * 2]);
            // Pass 3: lo*hi
#pragma unroll
            for (int mt = 0; mt < 2; ++mt)
#pragma unroll
                for (int nt = 0; nt < 4; ++nt)
                    mma16816(acc[mt][nt], afl[mt], &bfh[nt >> 1][(nt & 1) * 2]);
        }

        if (more) {
            cvtA(a4, stg ^ 1);
            CP_WAIT(0);
        }
        __syncthreads();
    }

    // Epilogue: add bias, store fp32 to g_xw
    const int g   = lane >> 2;
    const int tig = lane & 3;
#pragma unroll
    for (int mt = 0; mt < 2; ++mt) {
#pragma unroll
        for (int nt = 0; nt < 4; ++nt) {
            const int row = m0 + warp_m * 32 + mt * 16 + g;
            const int col = n0 + warp_n * 32 + nt * 8 + tig * 2;
            const float b0 = __ldg(bias + col);
            const float b1 = __ldg(bias + col + 1);
            float2 v0 = make_float2(acc[mt][nt][0] + b0, acc[mt][nt][1] + b1);
            float2 v1 = make_float2(acc[mt][nt][2] + b0, acc[mt][nt][3] + b1);
            *reinterpret_cast<float2*>(g_xw + (size_t)row * KDIM + col)       = v0;
            *reinterpret_cast<float2*>(g_xw + (size_t)(row + 8) * KDIM + col) = v1;
        }
    }
}

// ---------------------------------------------------------------------------
// Recurrent scan (validated): HW tanh.approx for recurrence + output sigmoid,
// PF=32 prefetch, streaming cache hints.
// ---------------------------------------------------------------------------
#define PF 32
__global__ __launch_bounds__(128)
void scan_kernel(const float* __restrict__ h0,
                 const float* __restrict__ dvec,
                 float* __restrict__ out,
                 int T, int BD, int D)
{
    const int idx = blockIdx.x * blockDim.x + threadIdx.x;
    if (idx >= BD) return;

    float dc = dvec[idx & (D - 1)];
    dc = fminf(fmaxf(dc, -0.99f), 0.99f);

    float h = h0[idx];
    float* __restrict__ out_h = out + (size_t)T * BD;
    __stcs(out_h + idx, h);

    const float* __restrict__ p = g_xw + idx;
    const size_t s = (size_t)BD;

    float cur[PF];
#pragma unroll
    for (int u = 0; u < PF; ++u) cur[u] = __ldcs(p + u * s);

    for (int t0 = 0; t0 < T; t0 += PF) {
        float nxt[PF];
        if (t0 + PF < T) {
            const float* pn = p + (size_t)(t0 + PF) * s;
#pragma unroll
            for (int u = 0; u < PF; ++u) nxt[u] = __ldcs(pn + u * s);
        } else {
#pragma unroll
            for (int u = 0; u < PF; ++u) nxt[u] = 0.0f;
        }
        float* __restrict__ po = out + (size_t)t0 * BD + idx;
        float* __restrict__ ph = out_h + (size_t)(t0 + 1) * BD + idx;
#pragma unroll
        for (int u = 0; u < PF; ++u) {
            const float z = fmaf(dc, h, cur[u]);
            asm("tanh.approx.f32 %0, %1;" : "=f"(h) : "f"(z));       // h = tanh(z)
            float th;
            asm("tanh.approx.f32 %0, %1;" : "=f"(th) : "f"(0.5f * h));
            const float sg = fmaf(0.5f, th, 0.5f);                    // sigmoid(h)
            __stcs(po + (size_t)u * BD, h * h * sg);                  // h * silu(h)
            __stcs(ph + (size_t)u * BD, h);
        }
#pragma unroll
        for (int u = 0; u < PF; ++u) cur[u] = nxt[u];
    }
}

// ---------------------------------------------------------------------------
// kernel_launch: splitW -> GEMM -> scan (serial).
// ---------------------------------------------------------------------------
extern "C" void kernel_launch(void* const* d_in, const int* in_sizes, int n_in,
                              void* d_out, int out_size)
{
    (void)n_in; (void)out_size;
    const float* x  = (const float*)d_in[0];
    const float* h0 = (const float*)d_in[1];
    const float* W  = (const float*)d_in[2];
    const float* dv = (const float*)d_in[3];
    const float* b  = (const float*)d_in[4];
    float* out = (float*)d_out;

    const int D  = in_sizes[3];           // 1024
    const int BD = in_sizes[1];           // 16384
    const int T  = in_sizes[0] / BD;      // 2048
    const int M  = in_sizes[0] / D;       // 32768

    const int nW4 = (D * D) / 4;
    splitW_kernel<<<(nW4 + 255) / 256, 256>>>((const float4*)W, nW4);

    cudaFuncSetAttribute(gemm_mma_kernel,
                         cudaFuncAttributeMaxDynamicSharedMemorySize, SMEM_TOTAL);
    dim3 grid(D / BN, M / BM);            // (8, 256)
    gemm_mma_kernel<<<grid, 512, SMEM_TOTAL>>>(x, b);

    scan_kernel<<<(BD + 127) / 128, 128>>>(h0, dv, out, T, BD, D);
}

// round 9
// speedup vs baseline: 1.3189x; 1.0630x over previous
#include <cuda_runtime.h>
#include <cuda_bf16.h>
#include <cstdint>
#include <math.h>

// ---------------------------------------------------------------------------
// Shapes (fixed): T=2048, B=16, D=1024.  M = T*B = 32768, K = N = 1024.
//   xw = x @ W_x^T + b  via mma.sync bf16 hi/lo split (3 MMAs), fp32 accum.
//   A and W pre-split fp32 -> bf16 hi/lo; GEMM stages all via cp.async.
//   scan: h_t = tanh(xw_t + d_c * h_{t-1}); out_t = h_t^2 * sigmoid(h_t)
//   d_out = [ output (T*B*D) | h ((T+1)*B*D) ]
// R9: 3-stage cp.async pipeline, pure-cp.async staging (8 ops/thread/ktile),
//     512-thread CTA, 3-pass MMA reorder; scan 2 chains/thread (float2).
// ---------------------------------------------------------------------------

#define KDIM 1024
#define BM 128
#define BN 128
#define BK 64                 // 64 bf16 = 128 B rows -> swizzled
#define NK (KDIM / BK)        // 16

__device__ __align__(128) float         g_xw [2048 * 16 * 1024];  // 128 MB
__device__ __align__(128) __nv_bfloat16 g_Ahi[32768 * 1024];      // 64 MB
__device__ __align__(128) __nv_bfloat16 g_Alo[32768 * 1024];      // 64 MB
__device__ __align__(128) __nv_bfloat16 g_Whi[1024 * 1024];       // 2 MB
__device__ __align__(128) __nv_bfloat16 g_Wlo[1024 * 1024];       // 2 MB

// ---------------------------------------------------------------------------
__device__ __forceinline__ void split4(float4 v, uint2& hi, uint2& lo) {
    __nv_bfloat16 hx = __float2bfloat16(v.x), hy = __float2bfloat16(v.y);
    __nv_bfloat16 hz = __float2bfloat16(v.z), hw = __float2bfloat16(v.w);
    __nv_bfloat16 lx = __float2bfloat16(v.x - __bfloat162float(hx));
    __nv_bfloat16 ly = __float2bfloat16(v.y - __bfloat162float(hy));
    __nv_bfloat16 lz = __float2bfloat16(v.z - __bfloat162float(hz));
    __nv_bfloat16 lw = __float2bfloat16(v.w - __bfloat162float(hw));
    __nv_bfloat162 h01 = __halves2bfloat162(hx, hy), h23 = __halves2bfloat162(hz, hw);
    __nv_bfloat162 l01 = __halves2bfloat162(lx, ly), l23 = __halves2bfloat162(lz, lw);
    hi.x = *reinterpret_cast<uint32_t*>(&h01); hi.y = *reinterpret_cast<uint32_t*>(&h23);
    lo.x = *reinterpret_cast<uint32_t*>(&l01); lo.y = *reinterpret_cast<uint32_t*>(&l23);
}
__global__ void splitA_kernel(const float4* __restrict__ src, int n4) {
    int i = blockIdx.x * blockDim.x + threadIdx.x;
    if (i >= n4) return;
    uint2 hi, lo; split4(src[i], hi, lo);
    reinterpret_cast<uint2*>(g_Ahi)[i] = hi;
    reinterpret_cast<uint2*>(g_Alo)[i] = lo;
}
__global__ void splitW_kernel(const float4* __restrict__ src, int n4) {
    int i = blockIdx.x * blockDim.x + threadIdx.x;
    if (i >= n4) return;
    uint2 hi, lo; split4(src[i], hi, lo);
    reinterpret_cast<uint2*>(g_Whi)[i] = hi;
    reinterpret_cast<uint2*>(g_Wlo)[i] = lo;
}

// ---------------------------------------------------------------------------
__device__ __forceinline__ uint32_t smem_u32(const void* p) {
    uint32_t a;
    asm("{ .reg .u64 t; cvta.to.shared.u64 t, %1; cvt.u32.u64 %0, t; }" : "=r"(a) : "l"(p));
    return a;
}
__device__ __forceinline__ void cp16(uint32_t dst, const void* src) {
    asm volatile("cp.async.cg.shared.global [%0], [%1], 16;" :: "r"(dst), "l"(src));
}
#define CP_COMMIT() asm volatile("cp.async.commit_group;" ::: "memory")
#define CP_WAIT(n)  asm volatile("cp.async.wait_group %0;" :: "n"(n) : "memory")

__device__ __forceinline__ void ldm_x4(uint32_t* r, uint32_t addr) {
    asm volatile("ldmatrix.sync.aligned.m8n8.x4.shared.b16 {%0,%1,%2,%3}, [%4];"
                 : "=r"(r[0]), "=r"(r[1]), "=r"(r[2]), "=r"(r[3]) : "r"(addr));
}
__device__ __forceinline__ void mma16816(float* d, const uint32_t* a,
                                         const uint32_t* b) {
    asm volatile(
        "mma.sync.aligned.m16n8k16.row.col.f32.bf16.bf16.f32 "
        "{%0,%1,%2,%3}, {%4,%5,%6,%7}, {%8,%9}, {%0,%1,%2,%3};"
        : "+f"(d[0]), "+f"(d[1]), "+f"(d[2]), "+f"(d[3])
        : "r"(a[0]), "r"(a[1]), "r"(a[2]), "r"(a[3]), "r"(b[0]), "r"(b[1]));
}

// SMEM: per stage: Ahi(16K) Alo(16K) Whi(16K) Wlo(16K) = 64 KB; 3 stages.
#define STG_BYTES   (64 * 1024)
#define OFF_AH      0
#define OFF_AL      (16 * 1024)
#define OFF_BH      (32 * 1024)
#define OFF_BL      (48 * 1024)
#define NSTG        3
#define SMEM_TOTAL  (NSTG * STG_BYTES)   // 192 KB

__device__ __forceinline__ uint32_t tswz(int row, int c) {
    return (uint32_t)(row * 128 + ((c ^ (row & 7)) * 16));
}

// ---------------------------------------------------------------------------
// GEMM: g_xw[m,n] = sum_k A[m,k]*W[n,k] + bias[n]
// 512 threads, 16 warps (4x4 grid of 32x32 warp tiles), pure cp.async staging,
// 3-stage pipeline, 3-pass reordered MMAs (8 independent accs per pass).
// ---------------------------------------------------------------------------
__global__ __launch_bounds__(512, 1)
void gemm_mma_kernel(const float* __restrict__ bias) {
    extern __shared__ char smem[];
    const uint32_t sb = smem_u32(smem);
    const int tid = threadIdx.x;
    const int wid = tid >> 5;
    const int lane = tid & 31;
    const int m0 = blockIdx.y * BM;
    const int n0 = blockIdx.x * BN;

    const int warp_m = wid & 3;    // 0..3 -> 32 rows
    const int warp_n = wid >> 2;   // 0..3 -> 32 cols

    // Stage loader: 512 threads; row = tid>>2 (0..127), chunks (tid&3)*2, +1.
    const int lrow = tid >> 2;
    const int lc0  = (tid & 3) * 2;

    auto stage_in = [&](int kt, int stg) {
        const uint32_t base = sb + stg * STG_BYTES;
        const size_t ga = (size_t)(m0 + lrow) * KDIM + kt * BK;
        const size_t gb = (size_t)(n0 + lrow) * KDIM + kt * BK;
#pragma unroll
        for (int j = 0; j < 2; ++j) {
            const int c = lc0 + j;
            const uint32_t so = tswz(lrow, c);
            cp16(base + OFF_AH + so, g_Ahi + ga + c * 8);
            cp16(base + OFF_AL + so, g_Alo + ga + c * 8);
            cp16(base + OFF_BH + so, g_Whi + gb + c * 8);
            cp16(base + OFF_BL + so, g_Wlo + gb + c * 8);
        }
        CP_COMMIT();
    };

    float acc[2][4][4];
#pragma unroll
    for (int i = 0; i < 2; ++i)
#pragma unroll
        for (int j = 0; j < 4; ++j)
#pragma unroll
            for (int q = 0; q < 4; ++q) acc[i][j][q] = 0.0f;

    // Prologue: stages 0 and 1 in flight.
    stage_in(0, 0);
    stage_in(1, 1);

    const int lmat  = lane >> 3;
    const int lrow8 = lane & 7;

    for (int kt = 0; kt < NK; ++kt) {
        CP_WAIT(1);              // group kt complete (kt+1 may be in flight)
        __syncthreads();         // also guards reuse of buffer (kt+2)%3

        if (kt + 2 < NK) stage_in(kt + 2, (kt + 2) % NSTG);

        const uint32_t base = sb + (kt % NSTG) * STG_BYTES;
#pragma unroll
        for (int kk = 0; kk < 4; ++kk) {
            uint32_t afh[2][4], afl[2][4];
#pragma unroll
            for (int mt = 0; mt < 2; ++mt) {
                const int r = warp_m * 32 + mt * 16 + (lmat & 1) * 8 + lrow8;
                const int c = 2 * kk + (lmat >> 1);
                const uint32_t so = tswz(r, c);
                ldm_x4(afh[mt], base + OFF_AH + so);
                ldm_x4(afl[mt], base + OFF_AL + so);
            }
            uint32_t bfh[2][4], bfl[2][4];
#pragma unroll
            for (int bt = 0; bt < 2; ++bt) {
                const int r = warp_n * 32 + bt * 16 + (lmat >> 1) * 8 + lrow8;
                const int c = 2 * kk + (lmat & 1);
                const uint32_t so = tswz(r, c);
                ldm_x4(bfh[bt], base + OFF_BH + so);
                ldm_x4(bfl[bt], base + OFF_BL + so);
            }
            // Pass 1: hi*hi — 8 independent accumulators.
#pragma unroll
            for (int mt = 0; mt < 2; ++mt)
#pragma unroll
                for (int nt = 0; nt < 4; ++nt)
                    mma16816(acc[mt][nt], afh[mt], &bfh[nt >> 1][(nt & 1) * 2]);
            // Pass 2: hi*lo
#pragma unroll
            for (int mt = 0; mt < 2; ++mt)
#pragma unroll
                for (int nt = 0; nt < 4; ++nt)
                    mma16816(acc[mt][nt], afh[mt], &bfl[nt >> 1][(nt & 1) * 2]);
            // Pass 3: lo*hi
#pragma unroll
            for (int mt = 0; mt < 2; ++mt)
#pragma unroll
                for (int nt = 0; nt < 4; ++nt)
                    mma16816(acc[mt][nt], afl[mt], &bfh[nt >> 1][(nt & 1) * 2]);
        }
    }

    // Epilogue: add bias, store fp32 to g_xw
    const int g   = lane >> 2;
    const int tig = lane & 3;
#pragma unroll
    for (int mt = 0; mt < 2; ++mt) {
#pragma unroll
        for (int nt = 0; nt < 4; ++nt) {
            const int row = m0 + warp_m * 32 + mt * 16 + g;
            const int col = n0 + warp_n * 32 + nt * 8 + tig * 2;
            const float b0 = __ldg(bias + col);
            const float b1 = __ldg(bias + col + 1);
            float2 v0 = make_float2(acc[mt][nt][0] + b0, acc[mt][nt][1] + b1);
            float2 v1 = make_float2(acc[mt][nt][2] + b0, acc[mt][nt][3] + b1);
            *reinterpret_cast<float2*>(g_xw + (size_t)row * KDIM + col)       = v0;
            *reinterpret_cast<float2*>(g_xw + (size_t)(row + 8) * KDIM + col) = v1;
        }
    }
}

// ---------------------------------------------------------------------------
// Recurrent scan: 2 chains per thread (float2 loads/stores), PF=16 blocks.
// HW tanh.approx for recurrence + output sigmoid (validated 1.05e-5).
// ---------------------------------------------------------------------------
#define PF 16
__global__ __launch_bounds__(128)
void scan_kernel(const float* __restrict__ h0,
                 const float* __restrict__ dvec,
                 float* __restrict__ out,
                 int T, int BD, int D)
{
    const int p2 = blockIdx.x * blockDim.x + threadIdx.x;   // pair index
    const int idx = p2 * 2;
    if (idx >= BD) return;

    float2 dc = *reinterpret_cast<const float2*>(dvec + (idx & (D - 1)));
    dc.x = fminf(fmaxf(dc.x, -0.99f), 0.99f);
    dc.y = fminf(fmaxf(dc.y, -0.99f), 0.99f);

    float2 h = *reinterpret_cast<const float2*>(h0 + idx);
    float* __restrict__ out_h = out + (size_t)T * BD;
    __stcs(reinterpret_cast<float2*>(out_h + idx), h);

    const float* __restrict__ p = g_xw + idx;
    const size_t s = (size_t)BD;

    float2 cur[PF];
#pragma unroll
    for (int u = 0; u < PF; ++u)
        cur[u] = __ldcs(reinterpret_cast<const float2*>(p + u * s));

    for (int t0 = 0; t0 < T; t0 += PF) {
        float2 nxt[PF];
        if (t0 + PF < T) {
            const float* pn = p + (size_t)(t0 + PF) * s;
#pragma unroll
            for (int u = 0; u < PF; ++u)
                nxt[u] = __ldcs(reinterpret_cast<const float2*>(pn + u * s));
        } else {
#pragma unroll
            for (int u = 0; u < PF; ++u) nxt[u] = make_float2(0.f, 0.f);
        }
        float* __restrict__ po = out + (size_t)t0 * BD + idx;
        float* __restrict__ ph = out_h + (size_t)(t0 + 1) * BD + idx;
#pragma unroll
        for (int u = 0; u < PF; ++u) {
            const float zx = fmaf(dc.x, h.x, cur[u].x);
            const float zy = fmaf(dc.y, h.y, cur[u].y);
            asm("tanh.approx.f32 %0, %1;" : "=f"(h.x) : "f"(zx));
            asm("tanh.approx.f32 %0, %1;" : "=f"(h.y) : "f"(zy));
            float tx, ty;
            asm("tanh.approx.f32 %0, %1;" : "=f"(tx) : "f"(0.5f * h.x));
            asm("tanh.approx.f32 %0, %1;" : "=f"(ty) : "f"(0.5f * h.y));
            float2 o;
            o.x = h.x * h.x * fmaf(0.5f, tx, 0.5f);
            o.y = h.y * h.y * fmaf(0.5f, ty, 0.5f);
            __stcs(reinterpret_cast<float2*>(po + (size_t)u * BD), o);
            __stcs(reinterpret_cast<float2*>(ph + (size_t)u * BD), h);
        }
#pragma unroll
        for (int u = 0; u < PF; ++u) cur[u] = nxt[u];
    }
}

// ---------------------------------------------------------------------------
// kernel_launch: splitA + splitW -> GEMM -> scan (serial).
// ---------------------------------------------------------------------------
extern "C" void kernel_launch(void* const* d_in, const int* in_sizes, int n_in,
                              void* d_out, int out_size)
{
    (void)n_in; (void)out_size;
    const float* x  = (const float*)d_in[0];
    const float* h0 = (const float*)d_in[1];
    const float* W  = (const float*)d_in[2];
    const float* dv = (const float*)d_in[3];
    const float* b  = (const float*)d_in[4];
    float* out = (float*)d_out;

    const int D  = in_sizes[3];           // 1024
    const int BD = in_sizes[1];           // 16384
    const int T  = in_sizes[0] / BD;      // 2048
    const int M  = in_sizes[0] / D;       // 32768

    const int nA4 = (M * D) / 4;
    splitA_kernel<<<nA4 / 256, 256>>>((const float4*)x, nA4);
    const int nW4 = (D * D) / 4;
    splitW_kernel<<<(nW4 + 255) / 256, 256>>>((const float4*)W, nW4);

    cudaFuncSetAttribute(gemm_mma_kernel,
                         cudaFuncAttributeMaxDynamicSharedMemorySize, SMEM_TOTAL);
    dim3 grid(D / BN, M / BM);            // (8, 256)
    gemm_mma_kernel<<<grid, 512, SMEM_TOTAL>>>(b);

    const int pairs = BD / 2;             // 8192
    scan_kernel<<<(pairs + 127) / 128, 128>>>(h0, dv, out, T, BD, D);
}

// round 10
// speedup vs baseline: 1.3283x; 1.0071x over previous
#include <cuda_runtime.h>
#include <cuda_bf16.h>
#include <cstdint>
#include <math.h>

// ---------------------------------------------------------------------------
// Shapes (fixed): T=2048, B=16, D=1024.  M = T*B = 32768, K = N = 1024.
//   xw = x @ W_x^T + b  via mma.sync bf16 hi/lo split (3 MMAs), fp32 accum.
//   A and W pre-split fp32 -> bf16 hi/lo; GEMM stages all via cp.async.
//   scan: h_t = tanh(xw_t + d_c * h_{t-1}); out_t = h_t^2 * sigmoid(h_t)
//   d_out = [ output (T*B*D) | h ((T+1)*B*D) ]
// R10: scan spread over 128 SMs (128x64); GEMM LDSM/MMA pass interleave.
// ---------------------------------------------------------------------------

#define KDIM 1024
#define BM 128
#define BN 128
#define BK 64                 // 64 bf16 = 128 B rows -> swizzled
#define NK (KDIM / BK)        // 16

__device__ __align__(128) float         g_xw [2048 * 16 * 1024];  // 128 MB
__device__ __align__(128) __nv_bfloat16 g_Ahi[32768 * 1024];      // 64 MB
__device__ __align__(128) __nv_bfloat16 g_Alo[32768 * 1024];      // 64 MB
__device__ __align__(128) __nv_bfloat16 g_Whi[1024 * 1024];       // 2 MB
__device__ __align__(128) __nv_bfloat16 g_Wlo[1024 * 1024];       // 2 MB

// ---------------------------------------------------------------------------
__device__ __forceinline__ void split4(float4 v, uint2& hi, uint2& lo) {
    __nv_bfloat16 hx = __float2bfloat16(v.x), hy = __float2bfloat16(v.y);
    __nv_bfloat16 hz = __float2bfloat16(v.z), hw = __float2bfloat16(v.w);
    __nv_bfloat16 lx = __float2bfloat16(v.x - __bfloat162float(hx));
    __nv_bfloat16 ly = __float2bfloat16(v.y - __bfloat162float(hy));
    __nv_bfloat16 lz = __float2bfloat16(v.z - __bfloat162float(hz));
    __nv_bfloat16 lw = __float2bfloat16(v.w - __bfloat162float(hw));
    __nv_bfloat162 h01 = __halves2bfloat162(hx, hy), h23 = __halves2bfloat162(hz, hw);
    __nv_bfloat162 l01 = __halves2bfloat162(lx, ly), l23 = __halves2bfloat162(lz, lw);
    hi.x = *reinterpret_cast<uint32_t*>(&h01); hi.y = *reinterpret_cast<uint32_t*>(&h23);
    lo.x = *reinterpret_cast<uint32_t*>(&l01); lo.y = *reinterpret_cast<uint32_t*>(&l23);
}
__global__ void splitA_kernel(const float4* __restrict__ src, int n4) {
    int i = blockIdx.x * blockDim.x + threadIdx.x;
    if (i >= n4) return;
    uint2 hi, lo; split4(src[i], hi, lo);
    reinterpret_cast<uint2*>(g_Ahi)[i] = hi;
    reinterpret_cast<uint2*>(g_Alo)[i] = lo;
}
__global__ void splitW_kernel(const float4* __restrict__ src, int n4) {
    int i = blockIdx.x * blockDim.x + threadIdx.x;
    if (i >= n4) return;
    uint2 hi, lo; split4(src[i], hi, lo);
    reinterpret_cast<uint2*>(g_Whi)[i] = hi;
    reinterpret_cast<uint2*>(g_Wlo)[i] = lo;
}

// ---------------------------------------------------------------------------
__device__ __forceinline__ uint32_t smem_u32(const void* p) {
    uint32_t a;
    asm("{ .reg .u64 t; cvta.to.shared.u64 t, %1; cvt.u32.u64 %0, t; }" : "=r"(a) : "l"(p));
    return a;
}
__device__ __forceinline__ void cp16(uint32_t dst, const void* src) {
    asm volatile("cp.async.cg.shared.global [%0], [%1], 16;" :: "r"(dst), "l"(src));
}
#define CP_COMMIT() asm volatile("cp.async.commit_group;" ::: "memory")
#define CP_WAIT(n)  asm volatile("cp.async.wait_group %0;" :: "n"(n) : "memory")

__device__ __forceinline__ void ldm_x4(uint32_t* r, uint32_t addr) {
    asm volatile("ldmatrix.sync.aligned.m8n8.x4.shared.b16 {%0,%1,%2,%3}, [%4];"
                 : "=r"(r[0]), "=r"(r[1]), "=r"(r[2]), "=r"(r[3]) : "r"(addr));
}
__device__ __forceinline__ void mma16816(float* d, const uint32_t* a,
                                         const uint32_t* b) {
    asm volatile(
        "mma.sync.aligned.m16n8k16.row.col.f32.bf16.bf16.f32 "
        "{%0,%1,%2,%3}, {%4,%5,%6,%7}, {%8,%9}, {%0,%1,%2,%3};"
        : "+f"(d[0]), "+f"(d[1]), "+f"(d[2]), "+f"(d[3])
        : "r"(a[0]), "r"(a[1]), "r"(a[2]), "r"(a[3]), "r"(b[0]), "r"(b[1]));
}

// SMEM: per stage: Ahi(16K) Alo(16K) Whi(16K) Wlo(16K) = 64 KB; 3 stages.
#define STG_BYTES   (64 * 1024)
#define OFF_AH      0
#define OFF_AL      (16 * 1024)
#define OFF_BH      (32 * 1024)
#define OFF_BL      (48 * 1024)
#define NSTG        3
#define SMEM_TOTAL  (NSTG * STG_BYTES)   // 192 KB

__device__ __forceinline__ uint32_t tswz(int row, int c) {
    return (uint32_t)(row * 128 + ((c ^ (row & 7)) * 16));
}

// ---------------------------------------------------------------------------
// GEMM: g_xw[m,n] = sum_k A[m,k]*W[n,k] + bias[n]
// 512 threads, 16 warps (4x4 grid of 32x32 warp tiles), pure cp.async staging,
// 3-stage pipeline. Per kk: LDSM interleaved with the 3 MMA passes so each
// pass hides the next pass's fragment-load latency.
// ---------------------------------------------------------------------------
__global__ __launch_bounds__(512, 1)
void gemm_mma_kernel(const float* __restrict__ bias) {
    extern __shared__ char smem[];
    const uint32_t sb = smem_u32(smem);
    const int tid = threadIdx.x;
    const int wid = tid >> 5;
    const int lane = tid & 31;
    const int m0 = blockIdx.y * BM;
    const int n0 = blockIdx.x * BN;

    const int warp_m = wid & 3;    // 0..3 -> 32 rows
    const int warp_n = wid >> 2;   // 0..3 -> 32 cols

    // Stage loader: 512 threads; row = tid>>2 (0..127), chunks (tid&3)*2, +1.
    const int lrow = tid >> 2;
    const int lc0  = (tid & 3) * 2;

    auto stage_in = [&](int kt, int stg) {
        const uint32_t base = sb + stg * STG_BYTES;
        const size_t ga = (size_t)(m0 + lrow) * KDIM + kt * BK;
        const size_t gb = (size_t)(n0 + lrow) * KDIM + kt * BK;
#pragma unroll
        for (int j = 0; j < 2; ++j) {
            const int c = lc0 + j;
            const uint32_t so = tswz(lrow, c);
            cp16(base + OFF_AH + so, g_Ahi + ga + c * 8);
            cp16(base + OFF_AL + so, g_Alo + ga + c * 8);
            cp16(base + OFF_BH + so, g_Whi + gb + c * 8);
            cp16(base + OFF_BL + so, g_Wlo + gb + c * 8);
        }
        CP_COMMIT();
    };

    float acc[2][4][4];
#pragma unroll
    for (int i = 0; i < 2; ++i)
#pragma unroll
        for (int j = 0; j < 4; ++j)
#pragma unroll
            for (int q = 0; q < 4; ++q) acc[i][j][q] = 0.0f;

    // Prologue: stages 0 and 1 in flight.
    stage_in(0, 0);
    stage_in(1, 1);

    const int lmat  = lane >> 3;
    const int lrow8 = lane & 7;

    for (int kt = 0; kt < NK; ++kt) {
        CP_WAIT(1);              // group kt complete (kt+1 may be in flight)
        __syncthreads();         // also guards reuse of buffer (kt+2)%3

        if (kt + 2 < NK) stage_in(kt + 2, (kt + 2) % NSTG);

        const uint32_t base = sb + (kt % NSTG) * STG_BYTES;
#pragma unroll
        for (int kk = 0; kk < 4; ++kk) {
            const int ca = 2 * kk + (lmat >> 1);   // A chunk column
            const int cb = 2 * kk + (lmat & 1);    // B chunk column
            const int ra0 = warp_m * 32 + (lmat & 1) * 8 + lrow8;
            const int rb0 = warp_n * 32 + (lmat >> 1) * 8 + lrow8;

            uint32_t afh[2][4], afl[2][4], bfh[2][4], bfl[2][4];
            // Fragments for pass 1 (+ bfl early so pass 1 hides its latency).
            ldm_x4(afh[0], base + OFF_AH + tswz(ra0,      ca));
            ldm_x4(afh[1], base + OFF_AH + tswz(ra0 + 16, ca));
            ldm_x4(bfh[0], base + OFF_BH + tswz(rb0,      cb));
            ldm_x4(bfh[1], base + OFF_BH + tswz(rb0 + 16, cb));
            ldm_x4(bfl[0], base + OFF_BL + tswz(rb0,      cb));
            ldm_x4(bfl[1], base + OFF_BL + tswz(rb0 + 16, cb));
            // Pass 1: hi*hi — 8 independent accumulators.
#pragma unroll
            for (int mt = 0; mt < 2; ++mt)
#pragma unroll
                for (int nt = 0; nt < 4; ++nt)
                    mma16816(acc[mt][nt], afh[mt], &bfh[nt >> 1][(nt & 1) * 2]);
            // afl loads hide under pass 2.
            ldm_x4(afl[0], base + OFF_AL + tswz(ra0,      ca));
            ldm_x4(afl[1], base + OFF_AL + tswz(ra0 + 16, ca));
            // Pass 2: hi*lo
#pragma unroll
            for (int mt = 0; mt < 2; ++mt)
#pragma unroll
                for (int nt = 0; nt < 4; ++nt)
                    mma16816(acc[mt][nt], afh[mt], &bfl[nt >> 1][(nt & 1) * 2]);
            // Pass 3: lo*hi
#pragma unroll
            for (int mt = 0; mt < 2; ++mt)
#pragma unroll
                for (int nt = 0; nt < 4; ++nt)
                    mma16816(acc[mt][nt], afl[mt], &bfh[nt >> 1][(nt & 1) * 2]);
        }
    }

    // Epilogue: add bias, store fp32 to g_xw
    const int g   = lane >> 2;
    const int tig = lane & 3;
#pragma unroll
    for (int mt = 0; mt < 2; ++mt) {
#pragma unroll
        for (int nt = 0; nt < 4; ++nt) {
            const int row = m0 + warp_m * 32 + mt * 16 + g;
            const int col = n0 + warp_n * 32 + nt * 8 + tig * 2;
            const float b0 = __ldg(bias + col);
            const float b1 = __ldg(bias + col + 1);
            float2 v0 = make_float2(acc[mt][nt][0] + b0, acc[mt][nt][1] + b1);
            float2 v1 = make_float2(acc[mt][nt][2] + b0, acc[mt][nt][3] + b1);
            *reinterpret_cast<float2*>(g_xw + (size_t)row * KDIM + col)       = v0;
            *reinterpret_cast<float2*>(g_xw + (size_t)(row + 8) * KDIM + col) = v1;
        }
    }
}

// ---------------------------------------------------------------------------
// Recurrent scan: 2 chains/thread (float2), 128 blocks x 64 threads so the
// LSU/L1tex queues of ~128 SMs are engaged (was 64 SMs). HW tanh.approx.
// ---------------------------------------------------------------------------
#define PF 16
__global__ __launch_bounds__(64)
void scan_kernel(const float* __restrict__ h0,
                 const float* __restrict__ dvec,
                 float* __restrict__ out,
                 int T, int BD, int D)
{
    const int p2 = blockIdx.x * blockDim.x + threadIdx.x;   // pair index
    const int idx = p2 * 2;
    if (idx >= BD) return;

    float2 dc = *reinterpret_cast<const float2*>(dvec + (idx & (D - 1)));
    dc.x = fminf(fmaxf(dc.x, -0.99f), 0.99f);
    dc.y = fminf(fmaxf(dc.y, -0.99f), 0.99f);

    float2 h = *reinterpret_cast<const float2*>(h0 + idx);
    float* __restrict__ out_h = out + (size_t)T * BD;
    __stcs(reinterpret_cast<float2*>(out_h + idx), h);

    const float* __restrict__ p = g_xw + idx;
    const size_t s = (size_t)BD;

    float2 cur[PF];
#pragma unroll
    for (int u = 0; u < PF; ++u)
        cur[u] = __ldcs(reinterpret_cast<const float2*>(p + u * s));

    for (int t0 = 0; t0 < T; t0 += PF) {
        float2 nxt[PF];
        if (t0 + PF < T) {
            const float* pn = p + (size_t)(t0 + PF) * s;
#pragma unroll
            for (int u = 0; u < PF; ++u)
                nxt[u] = __ldcs(reinterpret_cast<const float2*>(pn + u * s));
        } else {
#pragma unroll
            for (int u = 0; u < PF; ++u) nxt[u] = make_float2(0.f, 0.f);
        }
        float* __restrict__ po = out + (size_t)t0 * BD + idx;
        float* __restrict__ ph = out_h + (size_t)(t0 + 1) * BD + idx;
#pragma unroll
        for (int u = 0; u < PF; ++u) {
            const float zx = fmaf(dc.x, h.x, cur[u].x);
            const float zy = fmaf(dc.y, h.y, cur[u].y);
            asm("tanh.approx.f32 %0, %1;" : "=f"(h.x) : "f"(zx));
            asm("tanh.approx.f32 %0, %1;" : "=f"(h.y) : "f"(zy));
            float tx, ty;
            asm("tanh.approx.f32 %0, %1;" : "=f"(tx) : "f"(0.5f * h.x));
            asm("tanh.approx.f32 %0, %1;" : "=f"(ty) : "f"(0.5f * h.y));
            float2 o;
            o.x = h.x * h.x * fmaf(0.5f, tx, 0.5f);
            o.y = h.y * h.y * fmaf(0.5f, ty, 0.5f);
            __stcs(reinterpret_cast<float2*>(po + (size_t)u * BD), o);
            __stcs(reinterpret_cast<float2*>(ph + (size_t)u * BD), h);
        }
#pragma unroll
        for (int u = 0; u < PF; ++u) cur[u] = nxt[u];
    }
}

// ---------------------------------------------------------------------------
// kernel_launch: splitA + splitW -> GEMM -> scan (serial).
// ---------------------------------------------------------------------------
extern "C" void kernel_launch(void* const* d_in, const int* in_sizes, int n_in,
                              void* d_out, int out_size)
{
    (void)n_in; (void)out_size;
    const float* x  = (const float*)d_in[0];
    const float* h0 = (const float*)d_in[1];
    const float* W  = (const float*)d_in[2];
    const float* dv = (const float*)d_in[3];
    const float* b  = (const float*)d_in[4];
    float* out = (float*)d_out;

    const int D  = in_sizes[3];           // 1024
    const int BD = in_sizes[1];           // 16384
    const int T  = in_sizes[0] / BD;      // 2048
    const int M  = in_sizes[0] / D;       // 32768

    const int nA4 = (M * D) / 4;
    splitA_kernel<<<nA4 / 256, 256>>>((const float4*)x, nA4);
    const int nW4 = (D * D) / 4;
    splitW_kernel<<<(nW4 + 255) / 256, 256>>>((const float4*)W, nW4);

    cudaFuncSetAttribute(gemm_mma_kernel,
                         cudaFuncAttributeMaxDynamicSharedMemorySize, SMEM_TOTAL);
    dim3 grid(D / BN, M / BM);            // (8, 256)
    gemm_mma_kernel<<<grid, 512, SMEM_TOTAL>>>(b);

    const int pairs = BD / 2;             // 8192
    scan_kernel<<<pairs / 64, 64>>>(h0, dv, out, T, BD, D);
}

// round 11
// speedup vs baseline: 1.3357x; 1.0056x over previous
#include <cuda_runtime.h>
#include <cuda_bf16.h>
#include <cstdint>
#include <math.h>

// ---------------------------------------------------------------------------
// Shapes (fixed): T=2048, B=16, D=1024.  M = T*B = 32768, K = N = 1024.
//   xw = x @ W_x^T + b  via mma.sync bf16 hi/lo split (3 MMAs), fp32 accum.
//   A and W pre-split fp32 -> bf16 hi/lo; GEMM stages all via cp.async.
//   scan: h_t = tanh(xw_t + d_c * h_{t-1}); out_t = h_t^2 * sigmoid(h_t)
//   d_out = [ output (T*B*D) | h ((T+1)*B*D) ]
// R11: GEMM BN=256 (warp 32x64) halves smem traffic + syncs per FLOP;
//      scan output-sigmoid via odd polynomial (MUFU 4->2 per step).
// ---------------------------------------------------------------------------

#define KDIM 1024
#define BM 128
#define BN 256
#define BK 64                 // 64 bf16 = 128 B rows -> swizzled
#define NK (KDIM / BK)        // 16

__device__ __align__(128) float         g_xw [2048 * 16 * 1024];  // 128 MB
__device__ __align__(128) __nv_bfloat16 g_Ahi[32768 * 1024];      // 64 MB
__device__ __align__(128) __nv_bfloat16 g_Alo[32768 * 1024];      // 64 MB
__device__ __align__(128) __nv_bfloat16 g_Whi[1024 * 1024];       // 2 MB
__device__ __align__(128) __nv_bfloat16 g_Wlo[1024 * 1024];       // 2 MB

// ---------------------------------------------------------------------------
__device__ __forceinline__ void split4(float4 v, uint2& hi, uint2& lo) {
    __nv_bfloat16 hx = __float2bfloat16(v.x), hy = __float2bfloat16(v.y);
    __nv_bfloat16 hz = __float2bfloat16(v.z), hw = __float2bfloat16(v.w);
    __nv_bfloat16 lx = __float2bfloat16(v.x - __bfloat162float(hx));
    __nv_bfloat16 ly = __float2bfloat16(v.y - __bfloat162float(hy));
    __nv_bfloat16 lz = __float2bfloat16(v.z - __bfloat162float(hz));
    __nv_bfloat16 lw = __float2bfloat16(v.w - __bfloat162float(hw));
    __nv_bfloat162 h01 = __halves2bfloat162(hx, hy), h23 = __halves2bfloat162(hz, hw);
    __nv_bfloat162 l01 = __halves2bfloat162(lx, ly), l23 = __halves2bfloat162(lz, lw);
    hi.x = *reinterpret_cast<uint32_t*>(&h01); hi.y = *reinterpret_cast<uint32_t*>(&h23);
    lo.x = *reinterpret_cast<uint32_t*>(&l01); lo.y = *reinterpret_cast<uint32_t*>(&l23);
}
__global__ void splitA_kernel(const float4* __restrict__ src, int n4) {
    int i = blockIdx.x * blockDim.x + threadIdx.x;
    if (i >= n4) return;
    uint2 hi, lo; split4(src[i], hi, lo);
    reinterpret_cast<uint2*>(g_Ahi)[i] = hi;
    reinterpret_cast<uint2*>(g_Alo)[i] = lo;
}
__global__ void splitW_kernel(const float4* __restrict__ src, int n4) {
    int i = blockIdx.x * blockDim.x + threadIdx.x;
    if (i >= n4) return;
    uint2 hi, lo; split4(src[i], hi, lo);
    reinterpret_cast<uint2*>(g_Whi)[i] = hi;
    reinterpret_cast<uint2*>(g_Wlo)[i] = lo;
}

// ---------------------------------------------------------------------------
__device__ __forceinline__ uint32_t smem_u32(const void* p) {
    uint32_t a;
    asm("{ .reg .u64 t; cvta.to.shared.u64 t, %1; cvt.u32.u64 %0, t; }" : "=r"(a) : "l"(p));
    return a;
}
__device__ __forceinline__ void cp16(uint32_t dst, const void* src) {
    asm volatile("cp.async.cg.shared.global [%0], [%1], 16;" :: "r"(dst), "l"(src));
}
#define CP_COMMIT() asm volatile("cp.async.commit_group;" ::: "memory")
#define CP_WAIT(n)  asm volatile("cp.async.wait_group %0;" :: "n"(n) : "memory")

__device__ __forceinline__ void ldm_x4(uint32_t* r, uint32_t addr) {
    asm volatile("ldmatrix.sync.aligned.m8n8.x4.shared.b16 {%0,%1,%2,%3}, [%4];"
                 : "=r"(r[0]), "=r"(r[1]), "=r"(r[2]), "=r"(r[3]) : "r"(addr));
}
__device__ __forceinline__ void mma16816(float* d, const uint32_t* a,
                                         const uint32_t* b) {
    asm volatile(
        "mma.sync.aligned.m16n8k16.row.col.f32.bf16.bf16.f32 "
        "{%0,%1,%2,%3}, {%4,%5,%6,%7}, {%8,%9}, {%0,%1,%2,%3};"
        : "+f"(d[0]), "+f"(d[1]), "+f"(d[2]), "+f"(d[3])
        : "r"(a[0]), "r"(a[1]), "r"(a[2]), "r"(a[3]), "r"(b[0]), "r"(b[1]));
}

// SMEM per stage: Ahi(16K) Alo(16K) Bhi(32K) Blo(32K) = 96 KB; 2 stages.
#define STG_BYTES   (96 * 1024)
#define OFF_AH      0
#define OFF_AL      (16 * 1024)
#define OFF_BH      (32 * 1024)
#define OFF_BL      (64 * 1024)
#define NSTG        2
#define SMEM_TOTAL  (NSTG * STG_BYTES)   // 192 KB

__device__ __forceinline__ uint32_t tswz(int row, int c) {
    return (uint32_t)(row * 128 + ((c ^ (row & 7)) * 16));
}

// ---------------------------------------------------------------------------
// GEMM: g_xw[m,n] = sum_k A[m,k]*W[n,k] + bias[n]
// 512 threads, 16 warps in 4(m) x 4(n); warp tile 32x64 (acc[2][8][4]).
// Single cp.async group in flight; stage AFTER the barrier (race-free reuse).
// ---------------------------------------------------------------------------
__global__ __launch_bounds__(512, 1)
void gemm_mma_kernel(const float* __restrict__ bias) {
    extern __shared__ char smem[];
    const uint32_t sb = smem_u32(smem);
    const int tid = threadIdx.x;
    const int wid = tid >> 5;
    const int lane = tid & 31;
    const int m0 = blockIdx.y * BM;
    const int n0 = blockIdx.x * BN;

    const int warp_m = wid & 3;    // 0..3 -> 32 rows
    const int warp_n = wid >> 2;   // 0..3 -> 64 cols

    // Loaders: A 128 rows (4 thr/row, 2 chunks), B 256 rows (2 thr/row, 4 chunks)
    const int arow = tid >> 2;
    const int ac0  = (tid & 3) * 2;
    const int brow = tid >> 1;
    const int bc0  = (tid & 1) * 4;

    auto stage_in = [&](int kt, int stg) {
        const uint32_t base = sb + stg * STG_BYTES;
        const size_t ga = (size_t)(m0 + arow) * KDIM + kt * BK;
        const size_t gb = (size_t)(n0 + brow) * KDIM + kt * BK;
#pragma unroll
        for (int j = 0; j < 2; ++j) {
            const int c = ac0 + j;
            const uint32_t so = tswz(arow, c);
            cp16(base + OFF_AH + so, g_Ahi + ga + c * 8);
            cp16(base + OFF_AL + so, g_Alo + ga + c * 8);
        }
#pragma unroll
        for (int j = 0; j < 4; ++j) {
            const int c = bc0 + j;
            const uint32_t so = tswz(brow, c);
            cp16(base + OFF_BH + so, g_Whi + gb + c * 8);
            cp16(base + OFF_BL + so, g_Wlo + gb + c * 8);
        }
        CP_COMMIT();
    };

    float acc[2][8][4];
#pragma unroll
    for (int i = 0; i < 2; ++i)
#pragma unroll
        for (int j = 0; j < 8; ++j)
#pragma unroll
            for (int q = 0; q < 4; ++q) acc[i][j][q] = 0.0f;

    stage_in(0, 0);

    const int lmat  = lane >> 3;
    const int lrow8 = lane & 7;

    for (int kt = 0; kt < NK; ++kt) {
        CP_WAIT(0);              // group kt landed
        __syncthreads();         // all warps done reading the other buffer

        if (kt + 1 < NK) stage_in(kt + 1, (kt + 1) & 1);   // overlaps MMA below

        const uint32_t base = sb + (kt & 1) * STG_BYTES;
#pragma unroll
        for (int kk = 0; kk < 4; ++kk) {
            const int ca = 2 * kk + (lmat >> 1);
            const int cb = 2 * kk + (lmat & 1);
            const int ra0 = warp_m * 32 + (lmat & 1) * 8 + lrow8;

            uint32_t afh[2][4], afl[2][4];
            ldm_x4(afh[0], base + OFF_AH + tswz(ra0,      ca));
            ldm_x4(afh[1], base + OFF_AH + tswz(ra0 + 16, ca));
            ldm_x4(afl[0], base + OFF_AL + tswz(ra0,      ca));
            ldm_x4(afl[1], base + OFF_AL + tswz(ra0 + 16, ca));

#pragma unroll
            for (int c2 = 0; c2 < 2; ++c2) {   // two 32-col chunks of the 64-col warp tile
                const int rb0 = warp_n * 64 + c2 * 32 + (lmat >> 1) * 8 + lrow8;
                uint32_t bfh[2][4], bfl[2][4];
                ldm_x4(bfh[0], base + OFF_BH + tswz(rb0,      cb));
                ldm_x4(bfh[1], base + OFF_BH + tswz(rb0 + 16, cb));
                ldm_x4(bfl[0], base + OFF_BL + tswz(rb0,      cb));
                ldm_x4(bfl[1], base + OFF_BL + tswz(rb0 + 16, cb));
                // Pass 1: hi*hi — 8 independent accumulators
#pragma unroll
                for (int mt = 0; mt < 2; ++mt)
#pragma unroll
                    for (int nt = 0; nt < 4; ++nt)
                        mma16816(acc[mt][c2 * 4 + nt], afh[mt], &bfh[nt >> 1][(nt & 1) * 2]);
                // Pass 2: hi*lo
#pragma unroll
                for (int mt = 0; mt < 2; ++mt)
#pragma unroll
                    for (int nt = 0; nt < 4; ++nt)
                        mma16816(acc[mt][c2 * 4 + nt], afh[mt], &bfl[nt >> 1][(nt & 1) * 2]);
                // Pass 3: lo*hi
#pragma unroll
                for (int mt = 0; mt < 2; ++mt)
#pragma unroll
                    for (int nt = 0; nt < 4; ++nt)
                        mma16816(acc[mt][c2 * 4 + nt], afl[mt], &bfh[nt >> 1][(nt & 1) * 2]);
            }
        }
    }

    // Epilogue: add bias, store fp32 to g_xw
    const int g   = lane >> 2;
    const int tig = lane & 3;
#pragma unroll
    for (int mt = 0; mt < 2; ++mt) {
#pragma unroll
        for (int nt = 0; nt < 8; ++nt) {
            const int row = m0 + warp_m * 32 + mt * 16 + g;
            const int col = n0 + warp_n * 64 + nt * 8 + tig * 2;
            const float b0 = __ldg(bias + col);
            const float b1 = __ldg(bias + col + 1);
            float2 v0 = make_float2(acc[mt][nt][0] + b0, acc[mt][nt][1] + b1);
            float2 v1 = make_float2(acc[mt][nt][2] + b0, acc[mt][nt][3] + b1);
            *reinterpret_cast<float2*>(g_xw + (size_t)row * KDIM + col)       = v0;
            *reinterpret_cast<float2*>(g_xw + (size_t)(row + 8) * KDIM + col) = v1;
        }
    }
}

// ---------------------------------------------------------------------------
// Recurrent scan: 2 chains/thread (float2). Recurrence tanh = HW tanh.approx;
// output sigmoid = odd degree-7 polynomial on h in (-1,1) (err ~2e-5), on the
// idle FMA pipe. MUFU per step: 4 -> 2.
// ---------------------------------------------------------------------------
__device__ __forceinline__ float sig_poly(float h) {
    // sigmoid(h) = 0.5 + h/4 - h^3/48 + h^5/480 - 17h^7/80640, |h| < 1
    const float h2 = h * h;
    float p = fmaf(h2, -2.108134920e-4f, 2.083333333e-3f);
    p = fmaf(h2, p, -2.083333333e-2f);
    p = fmaf(h2, p, 2.5e-1f);
    return fmaf(h, p, 0.5f);
}

#define PF 16
__global__ __launch_bounds__(64)
void scan_kernel(const float* __restrict__ h0,
                 const float* __restrict__ dvec,
                 float* __restrict__ out,
                 int T, int BD, int D)
{
    const int p2 = blockIdx.x * blockDim.x + threadIdx.x;   // pair index
    const int idx = p2 * 2;
    if (idx >= BD) return;

    float2 dc = *reinterpret_cast<const float2*>(dvec + (idx & (D - 1)));
    dc.x = fminf(fmaxf(dc.x, -0.99f), 0.99f);
    dc.y = fminf(fmaxf(dc.y, -0.99f), 0.99f);

    float2 h = *reinterpret_cast<const float2*>(h0 + idx);
    float* __restrict__ out_h = out + (size_t)T * BD;
    __stcs(reinterpret_cast<float2*>(out_h + idx), h);

    const float* __restrict__ p = g_xw + idx;
    const size_t s = (size_t)BD;

    float2 cur[PF];
#pragma unroll
    for (int u = 0; u < PF; ++u)
        cur[u] = __ldcs(reinterpret_cast<const float2*>(p + u * s));

    for (int t0 = 0; t0 < T; t0 += PF) {
        float2 nxt[PF];
        if (t0 + PF < T) {
            const float* pn = p + (size_t)(t0 + PF) * s;
#pragma unroll
            for (int u = 0; u < PF; ++u)
                nxt[u] = __ldcs(reinterpret_cast<const float2*>(pn + u * s));
        } else {
#pragma unroll
            for (int u = 0; u < PF; ++u) nxt[u] = make_float2(0.f, 0.f);
        }
        float* __restrict__ po = out + (size_t)t0 * BD + idx;
        float* __restrict__ ph = out_h + (size_t)(t0 + 1) * BD + idx;
#pragma unroll
        for (int u = 0; u < PF; ++u) {
            const float zx = fmaf(dc.x, h.x, cur[u].x);
            const float zy = fmaf(dc.y, h.y, cur[u].y);
            asm("tanh.approx.f32 %0, %1;" : "=f"(h.x) : "f"(zx));
            asm("tanh.approx.f32 %0, %1;" : "=f"(h.y) : "f"(zy));
            float2 o;
            o.x = h.x * h.x * sig_poly(h.x);
            o.y = h.y * h.y * sig_poly(h.y);
            __stcs(reinterpret_cast<float2*>(po + (size_t)u * BD), o);
            __stcs(reinterpret_cast<float2*>(ph + (size_t)u * BD), h);
        }
#pragma unroll
        for (int u = 0; u < PF; ++u) cur[u] = nxt[u];
    }
}

// ---------------------------------------------------------------------------
// kernel_launch: splitA + splitW -> GEMM -> scan (serial).
// ---------------------------------------------------------------------------
extern "C" void kernel_launch(void* const* d_in, const int* in_sizes, int n_in,
                              void* d_out, int out_size)
{
    (void)n_in; (void)out_size;
    const float* x  = (const float*)d_in[0];
    const float* h0 = (const float*)d_in[1];
    const float* W  = (const float*)d_in[2];
    const float* dv = (const float*)d_in[3];
    const float* b  = (const float*)d_in[4];
    float* out = (float*)d_out;

    const int D  = in_sizes[3];           // 1024
    const int BD = in_sizes[1];           // 16384
    const int T  = in_sizes[0] / BD;      // 2048
    const int M  = in_sizes[0] / D;       // 32768

    const int nA4 = (M * D) / 4;
    splitA_kernel<<<nA4 / 256, 256>>>((const float4*)x, nA4);
    const int nW4 = (D * D) / 4;
    splitW_kernel<<<(nW4 + 255) / 256, 256>>>((const float4*)W, nW4);

    cudaFuncSetAttribute(gemm_mma_kernel,
                         cudaFuncAttributeMaxDynamicSharedMemorySize, SMEM_TOTAL);
    dim3 grid(D / BN, M / BM);            // (4, 256)
    gemm_mma_kernel<<<grid, 512, SMEM_TOTAL>>>(b);

    const int pairs = BD / 2;             // 8192
    scan_kernel<<<pairs / 64, 64>>>(h0, dv, out, T, BD, D);
}